// round 6
// baseline (speedup 1.0000x reference)
#include <cuda_runtime.h>
#include <math_constants.h>

#define BS          32
#define NUM_GT      64
#define NUM_PRIORS  8400
#define NUM_CLASSES 80
#define TOPK        9

// output layout (float32, concat of returned tuple)
#define OFF_L 0
#define OFF_B (BS*NUM_PRIORS)                       // 268800
#define OFF_S (OFF_B + BS*NUM_PRIORS*4)             // 1344000
#define OFF_F (OFF_S + BS*NUM_PRIORS*NUM_CLASSES)   // 22848000

typedef unsigned long long u64;

// static zero-init; k_out resets nonzero entries so every graph replay sees zeros.
__device__ u64 g_claims[BS*NUM_PRIORS];   // bit g set => gt g claimed this prior

// One warp per (b, gt). Priors are a regular grid per level; the top-9 closest
// centers provably lie in the 5x5 index window around the nearest grid node
// (d9 <= 1.5*sqrt(2)*s < 2.5*s = min distance of any cell at offset >= 3).
// One window cell per lane; top-9 found by warp-wide rank (keys unique).
__global__ __launch_bounds__(128) void k_select(
    const float4* __restrict__ gt_bboxes,
    const float*  __restrict__ pad_flag)
{
  const int wgl  = blockIdx.x*4 + (threadIdx.x >> 5);  // 0..2047
  const int b    = wgl >> 6;
  const int g    = wgl & 63;
  const int lane = threadIdx.x & 31;

  const float4 G = __ldg(&gt_bboxes[b*NUM_GT + g]);
  const float gcx = (G.x + G.z)*0.5f, gcy = (G.y + G.w)*0.5f;
  const float garea = (G.z - G.x)*(G.w - G.y);

  const int  qy = lane / 5;                 // 0..6 (lanes 25..31 invalid)
  const int  dxi = lane - qy*5 - 2;         // -2..2
  const int  dyi = qy - 2;
  const bool lane_ok = lane < 25;

  const int   Cn [3] = {80, 40, 20};
  const float Cs [3] = {8.f, 16.f, 32.f};
  const float Cis[3] = {0.125f, 0.0625f, 0.03125f};
  const int   Cst[3] = {0, 6400, 8000};

  float ov[3]; bool win[3]; float pxv[3], pyv[3]; int pidxv[3];
  float osum = 0.f;

  #pragma unroll
  for (int l = 0; l < 3; l++) {
    const int n = Cn[l]; const float s = Cs[l];
    const int jx0 = (int)floorf(gcx * Cis[l]);   // exact (power-of-two scale)
    const int jy0 = (int)floorf(gcy * Cis[l]);
    const int jx = jx0 + dxi, jy = jy0 + dyi;
    const bool v = lane_ok && (unsigned)jx < (unsigned)n && (unsigned)jy < (unsigned)n;

    const float px = ((float)jx + 0.5f) * s;     // == reference center, exact
    const float py = ((float)jy + 0.5f) * s;
    const float dx = gcx - px, dy = gcy - py;
    const float d  = fmaf(dx, dx, dy*dy);
    const int   pidx = Cst[l] + jy*n + jx;
    const u64 key = v ? (((u64)__float_as_uint(d) << 32) | (unsigned)pidx) : ~0ull;

    // rank = #keys strictly less (keys unique among valid lanes)
    int r = 0;
    #pragma unroll
    for (int src = 0; src < 25; src++) {
      u64 a = __shfl_sync(0xffffffffu, key, src);
      r += (a < key);
    }
    const bool w = v && (r < TOPK);   // >=16 valid cells always, so exactly 9 win
    win[l] = w; pxv[l] = px; pyv[l] = py; pidxv[l] = pidx;

    // candidate overlap (gt vs 5*stride cell), union clamped to 1e-6
    float o = 0.f;
    if (w) {
      const float h = 2.5f*s;
      const float x1 = px - h, x2 = px + h, y1 = py - h, y2 = py + h;
      float iw = fmaxf(fminf(G.z, x2) - fmaxf(G.x, x1), 0.f);
      float ih = fmaxf(fminf(G.w, y2) - fmaxf(G.y, y1), 0.f);
      float inter = iw*ih;
      float pa = (x2 - x1)*(y2 - y1);
      o = inter / fmaxf(garea + pa - inter, 1e-6f);
    }
    ov[l] = o;
    osum += o;
  }

  // thr = mean + std(ddof=1) over the 27 winner overlaps
  float ssum = osum;
  #pragma unroll
  for (int off = 16; off; off >>= 1) ssum += __shfl_xor_sync(0xffffffffu, ssum, off);
  const float mean = ssum / 27.f;
  float vsum = 0.f;
  #pragma unroll
  for (int l = 0; l < 3; l++)
    if (win[l]) { float e = ov[l] - mean; vsum = fmaf(e, e, vsum); }
  #pragma unroll
  for (int off = 16; off; off >>= 1) vsum += __shfl_xor_sync(0xffffffffu, vsum, off);
  const float thr = mean + sqrtf(vsum / 26.f);

  const bool pad = __ldg(&pad_flag[b*NUM_GT + g]) > 0.f;
  #pragma unroll
  for (int l = 0; l < 3; l++) {
    if (win[l] && pad && ov[l] > thr) {
      float m = fminf(fminf(pxv[l] - G.x, pyv[l] - G.y),
                      fminf(G.z - pxv[l], G.w - pyv[l]));
      if (m > 1e-9f)   // prior center strictly inside gt
        atomicOr(&g_claims[b*NUM_PRIORS + pidxv[l]], 1ull << g);
    }
  }
}

// analytic prior cell box from flat prior index
__device__ __forceinline__ float4 cell_box(int p) {
  int l = (p < 6400) ? 0 : (p < 8000 ? 1 : 2);
  int n = (l == 0) ? 80 : (l == 1 ? 40 : 20);
  float s = (l == 0) ? 8.f : (l == 1 ? 16.f : 32.f);
  int st = (l == 0) ? 0 : (l == 1 ? 6400 : 8000);
  int rel = p - st;
  int jy = rel / n, jx = rel - jy*n;
  float px = ((float)jx + 0.5f)*s, py = ((float)jy + 0.5f)*s;
  float h = 2.5f*s;
  return make_float4(px - h, py - h, px + h, py + h);
}

#define OT  256   // threads per block
#define PPT 2     // priors per thread; block covers OT*PPT = 512 keys

__global__ __launch_bounds__(OT) void k_out(
    const float4* __restrict__ gt_bboxes,
    const int*    __restrict__ gt_labels,
    const float4* __restrict__ pred,
    float* __restrict__ out)
{
  __shared__ float4 sgt [2*NUM_GT];
  __shared__ int    slab[2*NUM_GT];

  const int base = blockIdx.x * (OT*PPT);   // flat b*NUM_PRIORS+p space
  const int tid  = threadIdx.x;
  const int lane = tid & 31;

  const int lo   = base / NUM_PRIORS;               // first batch this block touches
  const int bnd  = (lo + 1) * NUM_PRIORS;           // boundary key of next batch

  // prefetch claims first (longest-latency independent loads)
  const int k0 = base + tid, k1 = base + OT + tid;
  u64 m0 = g_claims[k0];
  u64 m1 = g_claims[k1];
  if (m0) g_claims[k0] = 0;   // reset for next graph replay
  if (m1) g_claims[k1] = 0;

  // stage gt tables for the (<=2) batches this block spans
  if (tid < 2*NUM_GT) {
    const int bb = (tid < NUM_GT) ? lo : min(lo + 1, BS - 1);
    const int gg = tid & (NUM_GT - 1);
    sgt [tid] = __ldg(&gt_bboxes[bb*NUM_GT + gg]);
    slab[tid] = __ldg(&gt_labels[bb*NUM_GT + gg]);
  }
  __syncthreads();

  int   col[PPT];
  float val[PPT];

  #pragma unroll
  for (int q = 0; q < PPT; q++) {
    const int key  = base + q*OT + tid;
    const u64 m    = q ? m1 : m0;
    const int fg   = __popcll(m);
    const int toff = (key >= bnd) ? NUM_GT : 0;   // smem table offset

    int gi = 0;
    if (fg == 1) {
      gi = __ffsll((long long)m) - 1;
    } else if (fg > 1) {
      // resolve multi-claimed prior: first-max over ALL gts of gt-vs-cell IoU
      const int pb = (key >= bnd) ? lo + 1 : lo;
      float4 cb = cell_box(key - pb*NUM_PRIORS);
      float pa = (cb.z - cb.x)*(cb.w - cb.y);
      float best = -1.f;
      for (int gg = 0; gg < NUM_GT; gg++) {
        float4 T = sgt[toff + gg];
        float iw = fmaxf(fminf(T.z, cb.z) - fmaxf(T.x, cb.x), 0.f);
        float ih = fmaxf(fminf(T.w, cb.w) - fmaxf(T.y, cb.y), 0.f);
        float inter = iw*ih;
        float ga = (T.z - T.x)*(T.w - T.y);
        float ovl = inter / fmaxf(ga + pa - inter, 1e-6f);
        if (ovl > best) { best = ovl; gi = gg; }
      }
    }

    const float4 T = sgt[toff + gi];
    float labelv, fgm; int cl = -1; float vv = 0.f;
    if (fg > 0) {
      int lab = slab[toff + gi];
      labelv = (float)lab; cl = lab; fgm = 1.f;
      // score weight = IoU(gt, pred), union + 1e-9
      float4 P = __ldg(&pred[key]);
      float iw = fmaxf(fminf(T.z, P.z) - fmaxf(T.x, P.x), 0.f);
      float ih = fmaxf(fminf(T.w, P.w) - fmaxf(T.y, P.y), 0.f);
      float inter = iw*ih;
      float ga = (T.z - T.x)*(T.w - T.y);
      float pa = (P.z - P.x)*(P.w - P.y);
      vv = inter / (ga + pa - inter + 1e-9f);
    } else {
      labelv = (float)NUM_CLASSES; fgm = 0.f;   // background; bbox = gt[batch][0]
    }
    col[q] = cl; val[q] = vv;

    __stcs(&out[OFF_L + key], labelv);
    __stcs((float4*)out + (OFF_B >> 2) + key, T);
    __stcs(&out[OFF_F + key], fgm);
  }

  // score slabs: warp owns priors [keyw, keyw+32) per q => 640 contiguous float4s
  #pragma unroll
  for (int q = 0; q < PPT; q++) {
    const int keyw = (base + q*OT + tid) & ~31;
    float4* sco = (float4*)out + (OFF_S >> 2) + (size_t)keyw*(NUM_CLASSES/4);
    const int mycol = col[q]; const float myval = val[q];
    #pragma unroll
    for (int k = 0; k < 20; k++) {
      const int i  = lane + 32*k;
      const int lp = i / 20;
      const int c0 = (i - lp*20) * 4;
      const int   cl = __shfl_sync(0xffffffffu, mycol, lp);
      const float vv = __shfl_sync(0xffffffffu, myval, lp);
      float4 rr;
      rr.x = (cl == c0    ) ? vv : 0.f;
      rr.y = (cl == c0 + 1) ? vv : 0.f;
      rr.z = (cl == c0 + 2) ? vv : 0.f;
      rr.w = (cl == c0 + 3) ? vv : 0.f;
      __stcs(&sco[i], rr);
    }
  }
}

extern "C" void kernel_launch(void* const* d_in, const int* in_sizes, int n_in,
                              void* d_out, int out_size)
{
  const float4* pred = (const float4*)d_in[0];
  const int*    gtl  = (const int*)d_in[2];
  const float4* gtb  = (const float4*)d_in[3];
  const float*  pad  = (const float*)d_in[4];
  float* out = (float*)d_out;

  k_select<<<BS*NUM_GT/4, 128>>>(gtb, pad);
  k_out   <<<BS*NUM_PRIORS/(OT*PPT), OT>>>(gtb, gtl, pred, out);
}